// round 13
// baseline (speedup 1.0000x reference)
#include <cuda_runtime.h>
#include <cstdint>

// Problem constants
#define BSZ   4
#define SEQ   4096
#define BL    16384          // BSZ*SEQ tokens
#define DM    512            // d_model
#define DI    1024           // d_inner
#define DH    512            // d_half
#define DTR   32             // dt_rank
#define NST   16             // d_state
#define XDB   64             // dt_rank + 2*d_state

// Scratch pool (static device global: allocation-free at runtime)
#define OFF_XZ    0
#define OFF_XC    ((size_t)BL * DI)
#define OFF_YCAT  (OFF_XC + (size_t)BL * DH)
#define OFF_DELTA (OFF_YCAT + (size_t)BL * DI)
#define OFF_BP    (OFF_DELTA + (size_t)BL * DH)
#define OFF_CP    (OFF_BP + (size_t)BL * NST)
#define POOL_SZ   (OFF_CP + (size_t)BL * NST)
__device__ float g_pool[POOL_SZ];

typedef unsigned long long ull;

// ---------------------------------------------------------------------------
// SGEMM via packed fma.rn.f32x2 (2x fp32 FMA per issue slot on sm_100).
// C[M,N] = A[M,K] @ B[N,K]^T, row-major, K contiguous. Full fp32 precision.
// CTA 128x128, 256 threads, 8x8 per thread (as 8x4 f32x2 pairs), BK=8,
// double-buffered smem with register prefetch.
// A is stored DUPLICATED in smem ({a,a} pairs) so the broadcast operand
// loads directly as f32x2 with no packing instructions.
// Requires M%128==0, N%128==0, K%8==0.
// ---------------------------------------------------------------------------
#define ASW 264   // words per A smem row (256 data + 8 pad)
#define BSW 136   // words per B smem row (128 data + 8 pad)

__global__ __launch_bounds__(256) void sgemm_f32x2(
    const float* __restrict__ A, const float* __restrict__ B,
    float* __restrict__ C, int M, int N, int K)
{
    __shared__ float As[2][8][ASW];   // [k][2*m] duplicated
    __shared__ float Bs[2][8][BSW];   // [k][n]

    const int tid = threadIdx.x;
    const int bm = blockIdx.y * 128;
    const int bn = blockIdx.x * 128;

    // global load mapping: thread -> (row, 4 consecutive k)
    const int lrow = tid >> 1;            // 0..127
    const int lk   = (tid & 1) * 4;       // 0 or 4
    const float* Aptr = A + (size_t)(bm + lrow) * K + lk;
    const float* Bptr = B + (size_t)(bn + lrow) * K + lk;

    // compute mapping
    const int tx = tid & 15;              // n group
    const int ty = tid >> 4;              // m group
    const int tm0 = ty * 8;
    const int tn0 = tx * 8;

    ull acc2[8][4];
#pragma unroll
    for (int i = 0; i < 8; i++)
#pragma unroll
        for (int j = 0; j < 4; j++) acc2[i][j] = 0ull;

    float4 ra, rb;
    // preload tile 0
    ra = *(const float4*)(Aptr);
    rb = *(const float4*)(Bptr);
    {
        float av[4] = {ra.x, ra.y, ra.z, ra.w};
        float bv[4] = {rb.x, rb.y, rb.z, rb.w};
#pragma unroll
        for (int i = 0; i < 4; i++) {
            float2 d = make_float2(av[i], av[i]);
            *(float2*)&As[0][lk + i][2 * lrow] = d;
            Bs[0][lk + i][lrow] = bv[i];
        }
    }
    __syncthreads();

    int buf = 0;
    for (int kt = 0; kt < K; kt += 8) {
        const bool more = (kt + 8) < K;
        if (more) {
            ra = *(const float4*)(Aptr + kt + 8);
            rb = *(const float4*)(Bptr + kt + 8);
        }
#pragma unroll
        for (int kk = 0; kk < 8; kk++) {
            float4 a0 = *(const float4*)&As[buf][kk][2 * tm0];
            float4 a1 = *(const float4*)&As[buf][kk][2 * tm0 + 4];
            float4 a2 = *(const float4*)&As[buf][kk][2 * tm0 + 8];
            float4 a3 = *(const float4*)&As[buf][kk][2 * tm0 + 12];
            float4 b0 = *(const float4*)&Bs[buf][kk][tn0];
            float4 b1 = *(const float4*)&Bs[buf][kk][tn0 + 4];

            ull av2[8], bv2[4];
            av2[0] = ((const ull*)&a0)[0]; av2[1] = ((const ull*)&a0)[1];
            av2[2] = ((const ull*)&a1)[0]; av2[3] = ((const ull*)&a1)[1];
            av2[4] = ((const ull*)&a2)[0]; av2[5] = ((const ull*)&a2)[1];
            av2[6] = ((const ull*)&a3)[0]; av2[7] = ((const ull*)&a3)[1];
            bv2[0] = ((const ull*)&b0)[0]; bv2[1] = ((const ull*)&b0)[1];
            bv2[2] = ((const ull*)&b1)[0]; bv2[3] = ((const ull*)&b1)[1];

#pragma unroll
            for (int i = 0; i < 8; i++)
#pragma unroll
                for (int j = 0; j < 4; j++) {
                    asm("fma.rn.f32x2 %0, %1, %2, %0;"
                        : "+l"(acc2[i][j]) : "l"(av2[i]), "l"(bv2[j]));
                }
        }
        if (more) {
            const int nb = buf ^ 1;
            float av[4] = {ra.x, ra.y, ra.z, ra.w};
            float bv[4] = {rb.x, rb.y, rb.z, rb.w};
#pragma unroll
            for (int i = 0; i < 4; i++) {
                float2 d = make_float2(av[i], av[i]);
                *(float2*)&As[nb][lk + i][2 * lrow] = d;
                Bs[nb][lk + i][lrow] = bv[i];
            }
            __syncthreads();
            buf = nb;
        }
    }

    // epilogue: acc2[i][j] = {C[m_i][tn0+2j], C[m_i][tn0+2j+1]}
#pragma unroll
    for (int i = 0; i < 8; i++) {
        float* crow = C + (size_t)(bm + tm0 + i) * N + bn + tn0;
        *(float4*)(crow)     = *(const float4*)&acc2[i][0];
        *(float4*)(crow + 4) = *(const float4*)&acc2[i][2];
    }
}

// ---------------------------------------------------------------------------
// Depthwise conv(k=4, pad l=1 r=2) + SiLU. Vectorized weight/bias loads.
// x half -> xc; z half -> ycat[:, 512:1024]
// ---------------------------------------------------------------------------
__global__ __launch_bounds__(256) void conv_silu_kernel(
    const float* __restrict__ xz,
    const float* __restrict__ cxw, const float* __restrict__ cxb,
    const float* __restrict__ czw, const float* __restrict__ czb,
    float* __restrict__ xcout, float* __restrict__ ycat)
{
    int idx = blockIdx.x * 256 + threadIdx.x;
    int c4 = idx & 255;
    int t  = idx >> 8;
    int l  = t & (SEQ - 1);
    int c  = c4 * 4;

    const float* base = xz + (size_t)t * DI + c;
    float4 z4 = make_float4(0.f, 0.f, 0.f, 0.f);
    float4 s0 = (l >= 1)       ? *(const float4*)(base - DI)     : z4;
    float4 s1 =                  *(const float4*)(base);
    float4 s2 = (l + 1 < SEQ)  ? *(const float4*)(base + DI)     : z4;
    float4 s3 = (l + 2 < SEQ)  ? *(const float4*)(base + 2 * DI) : z4;

    float r0[4], r1[4], r2[4], r3[4];
    *(float4*)r0 = s0; *(float4*)r1 = s1; *(float4*)r2 = s2; *(float4*)r3 = s3;

    const bool isx = (c < DH);
    const int  cc  = isx ? c : (c - DH);
    const float* w  = (isx ? cxw : czw) + cc * 4;   // 16 consecutive floats
    const float* bb = (isx ? cxb : czb) + cc;       // 4 consecutive floats

    float Wf[16], Bf[4];
    *(float4*)(Wf + 0)  = *(const float4*)(w + 0);
    *(float4*)(Wf + 4)  = *(const float4*)(w + 4);
    *(float4*)(Wf + 8)  = *(const float4*)(w + 8);
    *(float4*)(Wf + 12) = *(const float4*)(w + 12);
    *(float4*)Bf        = *(const float4*)(bb);

    float out[4];
#pragma unroll
    for (int i = 0; i < 4; i++) {
        float v = Bf[i]
                + Wf[i * 4 + 0] * r0[i]
                + Wf[i * 4 + 1] * r1[i]
                + Wf[i * 4 + 2] * r2[i]
                + Wf[i * 4 + 3] * r3[i];
        float sg = __fdividef(1.f, 1.f + __expf(-v));
        out[i] = v * sg;
    }
    if (isx) *(float4*)(xcout + (size_t)t * DH + c) = *(float4*)out;
    else     *(float4*)(ycat  + (size_t)t * DI + c) = *(float4*)out;
}

// ---------------------------------------------------------------------------
// Fused: x_dbl = xc @ x_proj_w^T (64), LN(64), split Bp/Cp,
//        dt = clip(dt_raw @ dt_proj_w^T,-6,6), delta = softplus(dt+bias)
// ---------------------------------------------------------------------------
__global__ __launch_bounds__(256) void k3_kernel(
    const float* __restrict__ xc,  const float* __restrict__ xpw,
    const float* __restrict__ dtw, const float* __restrict__ dtb,
    const float* __restrict__ lnw, const float* __restrict__ lnb,
    float* __restrict__ delta, float* __restrict__ Bp, float* __restrict__ Cp)
{
    __shared__ float s_xc[16][DH];
    __shared__ float s_db[16][XDB];

    const int tid = threadIdx.x;
    const size_t tok0 = (size_t)blockIdx.x * 16;

    {
        const float4* src = (const float4*)(xc + tok0 * DH);
        float4* dst = (float4*)&s_xc[0][0];
#pragma unroll
        for (int i = 0; i < 8; i++) dst[tid + i * 256] = src[tid + i * 256];
    }
    __syncthreads();

    {
        const int j  = tid & 63;
        const int tg = tid >> 6;
        const float4* wr = (const float4*)(xpw + (size_t)j * DH);
        const float4* x0 = (const float4*)&s_xc[tg * 4 + 0][0];
        const float4* x1 = (const float4*)&s_xc[tg * 4 + 1][0];
        const float4* x2 = (const float4*)&s_xc[tg * 4 + 2][0];
        const float4* x3 = (const float4*)&s_xc[tg * 4 + 3][0];
        float a0 = 0.f, a1 = 0.f, a2 = 0.f, a3 = 0.f;
#pragma unroll 4
        for (int k = 0; k < DH / 4; k++) {
            float4 w4 = wr[k];
            float4 v0 = x0[k], v1 = x1[k], v2 = x2[k], v3 = x3[k];
            a0 += w4.x * v0.x + w4.y * v0.y + w4.z * v0.z + w4.w * v0.w;
            a1 += w4.x * v1.x + w4.y * v1.y + w4.z * v1.z + w4.w * v1.w;
            a2 += w4.x * v2.x + w4.y * v2.y + w4.z * v2.z + w4.w * v2.w;
            a3 += w4.x * v3.x + w4.y * v3.y + w4.z * v3.z + w4.w * v3.w;
        }
        s_db[tg * 4 + 0][j] = a0;
        s_db[tg * 4 + 1][j] = a1;
        s_db[tg * 4 + 2][j] = a2;
        s_db[tg * 4 + 3][j] = a3;
    }
    __syncthreads();

    {
        const int tok = tid >> 4;
        const int q   = tid & 15;
        const int j0  = q * 4;
        float v0 = s_db[tok][j0], v1 = s_db[tok][j0 + 1];
        float v2 = s_db[tok][j0 + 2], v3 = s_db[tok][j0 + 3];
        float s = v0 + v1 + v2 + v3;
        s += __shfl_xor_sync(0xffffffffu, s, 1);
        s += __shfl_xor_sync(0xffffffffu, s, 2);
        s += __shfl_xor_sync(0xffffffffu, s, 4);
        s += __shfl_xor_sync(0xffffffffu, s, 8);
        float mu = s * (1.f / 64.f);
        float d0 = v0 - mu, d1 = v1 - mu, d2 = v2 - mu, d3 = v3 - mu;
        float sq = d0 * d0 + d1 * d1 + d2 * d2 + d3 * d3;
        sq += __shfl_xor_sync(0xffffffffu, sq, 1);
        sq += __shfl_xor_sync(0xffffffffu, sq, 2);
        sq += __shfl_xor_sync(0xffffffffu, sq, 4);
        sq += __shfl_xor_sync(0xffffffffu, sq, 8);
        float rstd = rsqrtf(sq * (1.f / 64.f) + 1e-5f);
        float o[4];
        o[0] = d0 * rstd * lnw[j0]     + lnb[j0];
        o[1] = d1 * rstd * lnw[j0 + 1] + lnb[j0 + 1];
        o[2] = d2 * rstd * lnw[j0 + 2] + lnb[j0 + 2];
        o[3] = d3 * rstd * lnw[j0 + 3] + lnb[j0 + 3];
        s_db[tok][j0] = o[0]; s_db[tok][j0 + 1] = o[1];
        s_db[tok][j0 + 2] = o[2]; s_db[tok][j0 + 3] = o[3];
        if (q >= 8) {
            size_t tk = tok0 + tok;
            int base = j0 - DTR;
#pragma unroll
            for (int i = 0; i < 4; i++) {
                int jj = base + i;
                if (jj < NST) Bp[tk * NST + jj]         = o[i];
                else          Cp[tk * NST + (jj - NST)] = o[i];
            }
        }
    }
    __syncthreads();

    {
#pragma unroll
        for (int half = 0; half < 2; half++) {
            const int dch = tid + half * 256;
            const float4* wr = (const float4*)(dtw + (size_t)dch * DTR);
            float4 w4[8];
#pragma unroll
            for (int i = 0; i < 8; i++) w4[i] = wr[i];
            const float bias = dtb[dch];
#pragma unroll
            for (int tok = 0; tok < 16; tok++) {
                const float4* xr = (const float4*)&s_db[tok][0];
                float acc = 0.f;
#pragma unroll
                for (int i = 0; i < 8; i++) {
                    float4 x4 = xr[i];
                    acc += w4[i].x * x4.x + w4[i].y * x4.y
                         + w4[i].z * x4.z + w4[i].w * x4.w;
                }
                float v = fminf(fmaxf(acc, -6.f), 6.f) + bias;
                float sp = fmaxf(v, 0.f) + log1pf(__expf(-fabsf(v)));
                delta[(tok0 + tok) * (size_t)DH + dch] = sp;
            }
        }
    }
}

// ---------------------------------------------------------------------------
// Selective scan. Channel (b,d) = 16 lanes (one per state), 2 channels/warp.
// ---------------------------------------------------------------------------
__global__ __launch_bounds__(256) void scan_kernel(
    const float* __restrict__ delta, const float* __restrict__ xc,
    const float* __restrict__ Bp,    const float* __restrict__ Cp,
    const float* __restrict__ A_log, const float* __restrict__ D_param,
    float* __restrict__ ycat)
{
    const int tid = threadIdx.x;
    const int ch  = blockIdx.x * 16 + (tid >> 4);
    const int n   = tid & 15;
    const int b   = ch >> 9;
    const int d   = ch & 511;

    const float a  = -__expf(A_log[d * NST + n]);
    const float Dd = D_param[d];

    const float* dl = delta + ((size_t)b * SEQ) * DH + d;
    const float* ul = xc    + ((size_t)b * SEQ) * DH + d;
    const float* Bl = Bp    + ((size_t)b * SEQ) * NST + n;
    const float* Cl = Cp    + ((size_t)b * SEQ) * NST + n;
    float*       yl = ycat  + ((size_t)b * SEQ) * DI + d;

    float h = 0.f;
    float dv[2][4], uv[2][4], bv[2][4], cv[2][4];

#pragma unroll
    for (int i = 0; i < 4; i++) {
        dv[0][i] = dl[i * DH];  uv[0][i] = ul[i * DH];
        bv[0][i] = Bl[i * NST]; cv[0][i] = Cl[i * NST];
    }

    for (int l0 = 0; l0 < SEQ; l0 += 4) {
        const int cur = (l0 >> 2) & 1;
        const int nxt = cur ^ 1;
        if (l0 + 4 < SEQ) {
            const float* dn = dl + 4 * DH;
            const float* un = ul + 4 * DH;
            const float* bn = Bl + 4 * NST;
            const float* cn = Cl + 4 * NST;
#pragma unroll
            for (int i = 0; i < 4; i++) {
                dv[nxt][i] = dn[i * DH];  uv[nxt][i] = un[i * DH];
                bv[nxt][i] = bn[i * NST]; cv[nxt][i] = cn[i * NST];
            }
        }
#pragma unroll
        for (int i = 0; i < 4; i++) {
            float dvi = dv[cur][i];
            float da  = __expf(dvi * a);
            h = fmaf(da, h, dvi * uv[cur][i] * bv[cur][i]);
            float p = h * cv[cur][i];
            p += __shfl_xor_sync(0xffffffffu, p, 8);
            p += __shfl_xor_sync(0xffffffffu, p, 4);
            p += __shfl_xor_sync(0xffffffffu, p, 2);
            p += __shfl_xor_sync(0xffffffffu, p, 1);
            if (n == 0) yl[i * DI] = fmaf(Dd, uv[cur][i], p);
        }
        dl += 4 * DH; ul += 4 * DH; Bl += 4 * NST; Cl += 4 * NST; yl += 4 * DI;
    }
}

// ---------------------------------------------------------------------------
extern "C" void kernel_launch(void* const* d_in, const int* in_sizes, int n_in,
                              void* d_out, int out_size)
{
    const float* hs   = (const float*)d_in[0];
    const float* ipw  = (const float*)d_in[1];
    const float* xpw  = (const float*)d_in[2];
    const float* dtw  = (const float*)d_in[3];
    const float* dtb  = (const float*)d_in[4];
    const float* alog = (const float*)d_in[5];
    const float* Dp   = (const float*)d_in[6];
    const float* cxw  = (const float*)d_in[7];
    const float* cxb  = (const float*)d_in[8];
    const float* czw  = (const float*)d_in[9];
    const float* czb  = (const float*)d_in[10];
    const float* lnw  = (const float*)d_in[11];
    const float* lnb  = (const float*)d_in[12];
    const float* opw  = (const float*)d_in[13];

    float* pool = nullptr;
    cudaGetSymbolAddress((void**)&pool, g_pool);
    float* xz    = pool + OFF_XZ;
    float* xc    = pool + OFF_XC;
    float* ycat  = pool + OFF_YCAT;
    float* delta = pool + OFF_DELTA;
    float* Bpp   = pool + OFF_BP;
    float* Cpp   = pool + OFF_CP;

    // 1) xz = hs @ ipw^T   [16384,1024]   (fp32, packed f32x2 FMA)
    sgemm_f32x2<<<dim3(DI / 128, BL / 128), 256>>>(hs, ipw, xz, BL, DI, DM);
    // 2) depthwise conv + silu (x -> xc, z -> ycat[:,512:])
    conv_silu_kernel<<<BL, 256>>>(xz, cxw, cxb, czw, czb, xc, ycat);
    // 3) x_proj + LN + dt_proj + softplus
    k3_kernel<<<BL / 16, 256>>>(xc, xpw, dtw, dtb, lnw, lnb, delta, Bpp, Cpp);
    // 4) selective scan -> ycat[:, :512]
    scan_kernel<<<128, 256>>>(delta, xc, Bpp, Cpp, alog, Dp, ycat);
    // 5) out = ycat @ opw^T  [16384,512]
    sgemm_f32x2<<<dim3(DM / 128, BL / 128), 256>>>(ycat, opw, (float*)d_out, BL, DM, DI);
}

// round 14
// speedup vs baseline: 1.0990x; 1.0990x over previous
#include <cuda_runtime.h>
#include <cstdint>

// Problem constants
#define BSZ   4
#define SEQ   4096
#define BL    16384          // BSZ*SEQ tokens
#define DM    512            // d_model
#define DI    1024           // d_inner
#define DH    512            // d_half
#define DTR   32             // dt_rank
#define NST   16             // d_state
#define XDB   64             // dt_rank + 2*d_state

// Scratch pool (static device global: allocation-free at runtime)
#define OFF_XZ    0
#define OFF_XC    ((size_t)BL * DI)
#define OFF_YCAT  (OFF_XC + (size_t)BL * DH)
#define OFF_DELTA (OFF_YCAT + (size_t)BL * DI)
#define OFF_BP    (OFF_DELTA + (size_t)BL * DH)
#define OFF_CP    (OFF_BP + (size_t)BL * NST)
#define POOL_SZ   (OFF_CP + (size_t)BL * NST)
__device__ float g_pool[POOL_SZ];

// ---------------------------------------------------------------------------
// Tuned fp32 FFMA SGEMM: C[M,N] = A[M,K] @ B[N,K]^T (row-major, K contiguous)
// 128x128 tile, BK=16, 256 threads, 8x8/thread, double-buffered smem +
// register-pipelined fragments (load kk+1 frags during kk FFMAs).
// Requires M%128==0, N%128==0, K%16==0.
// ---------------------------------------------------------------------------
__global__ __launch_bounds__(256, 2) void sgemm_ffma(
    const float* __restrict__ A, const float* __restrict__ B,
    float* __restrict__ C, int M, int N, int K)
{
    __shared__ float As[2][16][128];
    __shared__ float Bs[2][16][128];

    const int tid = threadIdx.x;
    const int bm = blockIdx.y * 128;
    const int bn = blockIdx.x * 128;

    // global load mapping: thread -> (row, 8 consecutive k)
    const int lrow = tid >> 1;            // 0..127
    const int lk   = (tid & 1) * 8;       // 0 or 8
    const float* Aptr = A + (size_t)(bm + lrow) * K + lk;
    const float* Bptr = B + (size_t)(bn + lrow) * K + lk;

    // compute mapping: 16x16 thread grid, each 8(m) x 8(n)
    const int tx = tid & 15;
    const int ty = tid >> 4;
    const int tm0 = ty * 8;
    const int tn0 = tx * 8;

    float acc[8][8];
#pragma unroll
    for (int i = 0; i < 8; i++)
#pragma unroll
        for (int j = 0; j < 8; j++) acc[i][j] = 0.f;

    float4 ra0, ra1, rb0, rb1;

    // preload tile 0 into smem buffer 0
    ra0 = *(const float4*)(Aptr);
    ra1 = *(const float4*)(Aptr + 4);
    rb0 = *(const float4*)(Bptr);
    rb1 = *(const float4*)(Bptr + 4);
    {
        float av[8] = {ra0.x, ra0.y, ra0.z, ra0.w, ra1.x, ra1.y, ra1.z, ra1.w};
        float bv[8] = {rb0.x, rb0.y, rb0.z, rb0.w, rb1.x, rb1.y, rb1.z, rb1.w};
#pragma unroll
        for (int i = 0; i < 8; i++) {
            As[0][lk + i][lrow] = av[i];
            Bs[0][lk + i][lrow] = bv[i];
        }
    }
    __syncthreads();

    int buf = 0;
    for (int kt = 0; kt < K; kt += 16) {
        const bool more = (kt + 16) < K;
        if (more) {
            ra0 = *(const float4*)(Aptr + kt + 16);
            ra1 = *(const float4*)(Aptr + kt + 20);
            rb0 = *(const float4*)(Bptr + kt + 16);
            rb1 = *(const float4*)(Bptr + kt + 20);
        }

        // register-pipelined fragment loop over 16 k-slices
        float4 a0c = *(const float4*)&As[buf][0][tm0];
        float4 a1c = *(const float4*)&As[buf][0][tm0 + 4];
        float4 b0c = *(const float4*)&Bs[buf][0][tn0];
        float4 b1c = *(const float4*)&Bs[buf][0][tn0 + 4];
#pragma unroll
        for (int kk = 0; kk < 16; kk++) {
            float4 a0n, a1n, b0n, b1n;
            if (kk < 15) {
                a0n = *(const float4*)&As[buf][kk + 1][tm0];
                a1n = *(const float4*)&As[buf][kk + 1][tm0 + 4];
                b0n = *(const float4*)&Bs[buf][kk + 1][tn0];
                b1n = *(const float4*)&Bs[buf][kk + 1][tn0 + 4];
            }
            {
                float av[8] = {a0c.x, a0c.y, a0c.z, a0c.w,
                               a1c.x, a1c.y, a1c.z, a1c.w};
                float bv[8] = {b0c.x, b0c.y, b0c.z, b0c.w,
                               b1c.x, b1c.y, b1c.z, b1c.w};
#pragma unroll
                for (int i = 0; i < 8; i++)
#pragma unroll
                    for (int j = 0; j < 8; j++)
                        acc[i][j] = fmaf(av[i], bv[j], acc[i][j]);
            }
            a0c = a0n; a1c = a1n; b0c = b0n; b1c = b1n;
        }

        if (more) {
            const int nb = buf ^ 1;
            float av[8] = {ra0.x, ra0.y, ra0.z, ra0.w, ra1.x, ra1.y, ra1.z, ra1.w};
            float bv[8] = {rb0.x, rb0.y, rb0.z, rb0.w, rb1.x, rb1.y, rb1.z, rb1.w};
#pragma unroll
            for (int i = 0; i < 8; i++) {
                As[nb][lk + i][lrow] = av[i];
                Bs[nb][lk + i][lrow] = bv[i];
            }
            __syncthreads();
            buf = nb;
        }
    }

    // epilogue
#pragma unroll
    for (int i = 0; i < 8; i++) {
        float* crow = C + (size_t)(bm + tm0 + i) * N + bn + tn0;
        *(float4*)(crow)     = make_float4(acc[i][0], acc[i][1], acc[i][2], acc[i][3]);
        *(float4*)(crow + 4) = make_float4(acc[i][4], acc[i][5], acc[i][6], acc[i][7]);
    }
}

// ---------------------------------------------------------------------------
// Depthwise conv(k=4, pad l=1 r=2) + SiLU. Vectorized weight/bias loads.
// x half -> xc; z half -> ycat[:, 512:1024]
// ---------------------------------------------------------------------------
__global__ __launch_bounds__(256) void conv_silu_kernel(
    const float* __restrict__ xz,
    const float* __restrict__ cxw, const float* __restrict__ cxb,
    const float* __restrict__ czw, const float* __restrict__ czb,
    float* __restrict__ xcout, float* __restrict__ ycat)
{
    int idx = blockIdx.x * 256 + threadIdx.x;
    int c4 = idx & 255;
    int t  = idx >> 8;
    int l  = t & (SEQ - 1);
    int c  = c4 * 4;

    const float* base = xz + (size_t)t * DI + c;
    float4 z4 = make_float4(0.f, 0.f, 0.f, 0.f);
    float4 s0 = (l >= 1)       ? *(const float4*)(base - DI)     : z4;
    float4 s1 =                  *(const float4*)(base);
    float4 s2 = (l + 1 < SEQ)  ? *(const float4*)(base + DI)     : z4;
    float4 s3 = (l + 2 < SEQ)  ? *(const float4*)(base + 2 * DI) : z4;

    float r0[4], r1[4], r2[4], r3[4];
    *(float4*)r0 = s0; *(float4*)r1 = s1; *(float4*)r2 = s2; *(float4*)r3 = s3;

    const bool isx = (c < DH);
    const int  cc  = isx ? c : (c - DH);
    const float* w  = (isx ? cxw : czw) + cc * 4;
    const float* bb = (isx ? cxb : czb) + cc;

    float Wf[16], Bf[4];
    *(float4*)(Wf + 0)  = *(const float4*)(w + 0);
    *(float4*)(Wf + 4)  = *(const float4*)(w + 4);
    *(float4*)(Wf + 8)  = *(const float4*)(w + 8);
    *(float4*)(Wf + 12) = *(const float4*)(w + 12);
    *(float4*)Bf        = *(const float4*)(bb);

    float out[4];
#pragma unroll
    for (int i = 0; i < 4; i++) {
        float v = Bf[i]
                + Wf[i * 4 + 0] * r0[i]
                + Wf[i * 4 + 1] * r1[i]
                + Wf[i * 4 + 2] * r2[i]
                + Wf[i * 4 + 3] * r3[i];
        float sg = __fdividef(1.f, 1.f + __expf(-v));
        out[i] = v * sg;
    }
    if (isx) *(float4*)(xcout + (size_t)t * DH + c) = *(float4*)out;
    else     *(float4*)(ycat  + (size_t)t * DI + c) = *(float4*)out;
}

// ---------------------------------------------------------------------------
// Fused: x_dbl = xc @ x_proj_w^T (64), LN(64), split Bp/Cp,
//        dt = clip(dt_raw @ dt_proj_w^T,-6,6), delta = softplus(dt+bias)
// ---------------------------------------------------------------------------
__global__ __launch_bounds__(256) void k3_kernel(
    const float* __restrict__ xc,  const float* __restrict__ xpw,
    const float* __restrict__ dtw, const float* __restrict__ dtb,
    const float* __restrict__ lnw, const float* __restrict__ lnb,
    float* __restrict__ delta, float* __restrict__ Bp, float* __restrict__ Cp)
{
    __shared__ float s_xc[16][DH];
    __shared__ float s_db[16][XDB];

    const int tid = threadIdx.x;
    const size_t tok0 = (size_t)blockIdx.x * 16;

    {
        const float4* src = (const float4*)(xc + tok0 * DH);
        float4* dst = (float4*)&s_xc[0][0];
#pragma unroll
        for (int i = 0; i < 8; i++) dst[tid + i * 256] = src[tid + i * 256];
    }
    __syncthreads();

    {
        const int j  = tid & 63;
        const int tg = tid >> 6;
        const float4* wr = (const float4*)(xpw + (size_t)j * DH);
        const float4* x0 = (const float4*)&s_xc[tg * 4 + 0][0];
        const float4* x1 = (const float4*)&s_xc[tg * 4 + 1][0];
        const float4* x2 = (const float4*)&s_xc[tg * 4 + 2][0];
        const float4* x3 = (const float4*)&s_xc[tg * 4 + 3][0];
        float a0 = 0.f, a1 = 0.f, a2 = 0.f, a3 = 0.f;
#pragma unroll 4
        for (int k = 0; k < DH / 4; k++) {
            float4 w4 = wr[k];
            float4 v0 = x0[k], v1 = x1[k], v2 = x2[k], v3 = x3[k];
            a0 += w4.x * v0.x + w4.y * v0.y + w4.z * v0.z + w4.w * v0.w;
            a1 += w4.x * v1.x + w4.y * v1.y + w4.z * v1.z + w4.w * v1.w;
            a2 += w4.x * v2.x + w4.y * v2.y + w4.z * v2.z + w4.w * v2.w;
            a3 += w4.x * v3.x + w4.y * v3.y + w4.z * v3.z + w4.w * v3.w;
        }
        s_db[tg * 4 + 0][j] = a0;
        s_db[tg * 4 + 1][j] = a1;
        s_db[tg * 4 + 2][j] = a2;
        s_db[tg * 4 + 3][j] = a3;
    }
    __syncthreads();

    {
        const int tok = tid >> 4;
        const int q   = tid & 15;
        const int j0  = q * 4;
        float v0 = s_db[tok][j0], v1 = s_db[tok][j0 + 1];
        float v2 = s_db[tok][j0 + 2], v3 = s_db[tok][j0 + 3];
        float s = v0 + v1 + v2 + v3;
        s += __shfl_xor_sync(0xffffffffu, s, 1);
        s += __shfl_xor_sync(0xffffffffu, s, 2);
        s += __shfl_xor_sync(0xffffffffu, s, 4);
        s += __shfl_xor_sync(0xffffffffu, s, 8);
        float mu = s * (1.f / 64.f);
        float d0 = v0 - mu, d1 = v1 - mu, d2 = v2 - mu, d3 = v3 - mu;
        float sq = d0 * d0 + d1 * d1 + d2 * d2 + d3 * d3;
        sq += __shfl_xor_sync(0xffffffffu, sq, 1);
        sq += __shfl_xor_sync(0xffffffffu, sq, 2);
        sq += __shfl_xor_sync(0xffffffffu, sq, 4);
        sq += __shfl_xor_sync(0xffffffffu, sq, 8);
        float rstd = rsqrtf(sq * (1.f / 64.f) + 1e-5f);
        float o[4];
        o[0] = d0 * rstd * lnw[j0]     + lnb[j0];
        o[1] = d1 * rstd * lnw[j0 + 1] + lnb[j0 + 1];
        o[2] = d2 * rstd * lnw[j0 + 2] + lnb[j0 + 2];
        o[3] = d3 * rstd * lnw[j0 + 3] + lnb[j0 + 3];
        s_db[tok][j0] = o[0]; s_db[tok][j0 + 1] = o[1];
        s_db[tok][j0 + 2] = o[2]; s_db[tok][j0 + 3] = o[3];
        if (q >= 8) {
            size_t tk = tok0 + tok;
            int base = j0 - DTR;
#pragma unroll
            for (int i = 0; i < 4; i++) {
                int jj = base + i;
                if (jj < NST) Bp[tk * NST + jj]         = o[i];
                else          Cp[tk * NST + (jj - NST)] = o[i];
            }
        }
    }
    __syncthreads();

    {
#pragma unroll
        for (int half = 0; half < 2; half++) {
            const int dch = tid + half * 256;
            const float4* wr = (const float4*)(dtw + (size_t)dch * DTR);
            float4 w4[8];
#pragma unroll
            for (int i = 0; i < 8; i++) w4[i] = wr[i];
            const float bias = dtb[dch];
#pragma unroll
            for (int tok = 0; tok < 16; tok++) {
                const float4* xr = (const float4*)&s_db[tok][0];
                float acc = 0.f;
#pragma unroll
                for (int i = 0; i < 8; i++) {
                    float4 x4 = xr[i];
                    acc += w4[i].x * x4.x + w4[i].y * x4.y
                         + w4[i].z * x4.z + w4[i].w * x4.w;
                }
                float v = fminf(fmaxf(acc, -6.f), 6.f) + bias;
                float sp = fmaxf(v, 0.f) + log1pf(__expf(-fabsf(v)));
                delta[(tok0 + tok) * (size_t)DH + dch] = sp;
            }
        }
    }
}

// ---------------------------------------------------------------------------
// Selective scan. Channel (b,d) = 16 lanes (one per state), 2 channels/warp.
// ---------------------------------------------------------------------------
__global__ __launch_bounds__(256) void scan_kernel(
    const float* __restrict__ delta, const float* __restrict__ xc,
    const float* __restrict__ Bp,    const float* __restrict__ Cp,
    const float* __restrict__ A_log, const float* __restrict__ D_param,
    float* __restrict__ ycat)
{
    const int tid = threadIdx.x;
    const int ch  = blockIdx.x * 16 + (tid >> 4);
    const int n   = tid & 15;
    const int b   = ch >> 9;
    const int d   = ch & 511;

    const float a  = -__expf(A_log[d * NST + n]);
    const float Dd = D_param[d];

    const float* dl = delta + ((size_t)b * SEQ) * DH + d;
    const float* ul = xc    + ((size_t)b * SEQ) * DH + d;
    const float* Bl = Bp    + ((size_t)b * SEQ) * NST + n;
    const float* Cl = Cp    + ((size_t)b * SEQ) * NST + n;
    float*       yl = ycat  + ((size_t)b * SEQ) * DI + d;

    float h = 0.f;
    float dv[2][4], uv[2][4], bv[2][4], cv[2][4];

#pragma unroll
    for (int i = 0; i < 4; i++) {
        dv[0][i] = dl[i * DH];  uv[0][i] = ul[i * DH];
        bv[0][i] = Bl[i * NST]; cv[0][i] = Cl[i * NST];
    }

    for (int l0 = 0; l0 < SEQ; l0 += 4) {
        const int cur = (l0 >> 2) & 1;
        const int nxt = cur ^ 1;
        if (l0 + 4 < SEQ) {
            const float* dn = dl + 4 * DH;
            const float* un = ul + 4 * DH;
            const float* bn = Bl + 4 * NST;
            const float* cn = Cl + 4 * NST;
#pragma unroll
            for (int i = 0; i < 4; i++) {
                dv[nxt][i] = dn[i * DH];  uv[nxt][i] = un[i * DH];
                bv[nxt][i] = bn[i * NST]; cv[nxt][i] = cn[i * NST];
            }
        }
#pragma unroll
        for (int i = 0; i < 4; i++) {
            float dvi = dv[cur][i];
            float da  = __expf(dvi * a);
            h = fmaf(da, h, dvi * uv[cur][i] * bv[cur][i]);
            float p = h * cv[cur][i];
            p += __shfl_xor_sync(0xffffffffu, p, 8);
            p += __shfl_xor_sync(0xffffffffu, p, 4);
            p += __shfl_xor_sync(0xffffffffu, p, 2);
            p += __shfl_xor_sync(0xffffffffu, p, 1);
            if (n == 0) yl[i * DI] = fmaf(Dd, uv[cur][i], p);
        }
        dl += 4 * DH; ul += 4 * DH; Bl += 4 * NST; Cl += 4 * NST; yl += 4 * DI;
    }
}

// ---------------------------------------------------------------------------
extern "C" void kernel_launch(void* const* d_in, const int* in_sizes, int n_in,
                              void* d_out, int out_size)
{
    const float* hs   = (const float*)d_in[0];
    const float* ipw  = (const float*)d_in[1];
    const float* xpw  = (const float*)d_in[2];
    const float* dtw  = (const float*)d_in[3];
    const float* dtb  = (const float*)d_in[4];
    const float* alog = (const float*)d_in[5];
    const float* Dp   = (const float*)d_in[6];
    const float* cxw  = (const float*)d_in[7];
    const float* cxb  = (const float*)d_in[8];
    const float* czw  = (const float*)d_in[9];
    const float* czb  = (const float*)d_in[10];
    const float* lnw  = (const float*)d_in[11];
    const float* lnb  = (const float*)d_in[12];
    const float* opw  = (const float*)d_in[13];

    float* pool = nullptr;
    cudaGetSymbolAddress((void**)&pool, g_pool);
    float* xz    = pool + OFF_XZ;
    float* xc    = pool + OFF_XC;
    float* ycat  = pool + OFF_YCAT;
    float* delta = pool + OFF_DELTA;
    float* Bpp   = pool + OFF_BP;
    float* Cpp   = pool + OFF_CP;

    // 1) xz = hs @ ipw^T   [16384,1024]   (fp32 FFMA, register-pipelined)
    sgemm_ffma<<<dim3(DI / 128, BL / 128), 256>>>(hs, ipw, xz, BL, DI, DM);
    // 2) depthwise conv + silu (x -> xc, z -> ycat[:,512:])
    conv_silu_kernel<<<BL, 256>>>(xz, cxw, cxb, czw, czb, xc, ycat);
    // 3) x_proj + LN + dt_proj + softplus
    k3_kernel<<<BL / 16, 256>>>(xc, xpw, dtw, dtb, lnw, lnb, delta, Bpp, Cpp);
    // 4) selective scan -> ycat[:, :512]
    scan_kernel<<<128, 256>>>(delta, xc, Bpp, Cpp, alog, Dp, ycat);
    // 5) out = ycat @ opw^T  [16384,512]
    sgemm_ffma<<<dim3(DM / 128, BL / 128), 256>>>(ycat, opw, (float*)d_out, BL, DM, DI);
}

// round 17
// speedup vs baseline: 1.5035x; 1.3681x over previous
#include <cuda_runtime.h>
#include <cuda_fp16.h>
#include <cstdint>

// Problem constants
#define BSZ   4
#define SEQ   4096
#define BL    16384          // BSZ*SEQ tokens
#define DM    512            // d_model
#define DI    1024           // d_inner
#define DH    512            // d_half
#define DTR   32             // dt_rank
#define NST   16             // d_state
#define XDB   64             // dt_rank + 2*d_state

// Scratch pool (static device global: allocation-free at runtime)
#define OFF_XZ    0
#define OFF_XC    ((size_t)BL * DI)
#define OFF_YCAT  (OFF_XC + (size_t)BL * DH)
#define OFF_DELTA (OFF_YCAT + (size_t)BL * DI)
#define OFF_BP    (OFF_DELTA + (size_t)BL * DH)
#define OFF_CP    (OFF_BP + (size_t)BL * NST)
#define OFF_HACT  (OFF_CP + (size_t)BL * NST)          // fp16 activations (BL*DI halves)
#define OFF_HW    (OFF_HACT + (size_t)BL * DI / 2)     // fp16 weights (DI*DM halves)
#define POOL_SZ   (OFF_HW + (size_t)DI * DM / 2)
__device__ float g_pool[POOL_SZ];

// ---------------------------------------------------------------------------
// Helpers
// ---------------------------------------------------------------------------
__device__ __forceinline__ uint32_t sm_u32(const void* p) {
    return (uint32_t)__cvta_generic_to_shared(p);
}
__device__ __forceinline__ void cp16(uint32_t dst, const void* src) {
    asm volatile("cp.async.cg.shared.global [%0], [%1], 16;" :: "r"(dst), "l"(src));
}

// ---------------------------------------------------------------------------
// fp32 -> fp16 conversion (rn)
// ---------------------------------------------------------------------------
__global__ __launch_bounds__(256) void to_half_kernel(
    const float* __restrict__ in, __half* __restrict__ out, int n4)
{
    int i = blockIdx.x * 256 + threadIdx.x;
    if (i < n4) {
        float4 v = ((const float4*)in)[i];
        __half2 h0 = __floats2half2_rn(v.x, v.y);
        __half2 h1 = __floats2half2_rn(v.z, v.w);
        ((__half2*)out)[2 * i]     = h0;
        ((__half2*)out)[2 * i + 1] = h1;
    }
}

// ---------------------------------------------------------------------------
// FP16 mma.sync GEMM with ldmatrix fragment loads.
// C[M,N] = A[M,K] @ B[N,K]^T (fp16 in, fp32 out/acc)
// CTA 128x128, 4 warps (2x2), warp tile 64x64, BK=32 halves, 4-stage cp.async.
// Smem [row][k], row stride 40 halves (80B) -> ldmatrix rows hit distinct banks.
// Requires M%128==0, N%128==0, K%32==0.
// ---------------------------------------------------------------------------
#define HG_RSH   40                        // halves per smem row
#define HG_OPB   (128 * HG_RSH * 2)        // bytes per operand per stage (10240)
#define HG_STAGES 4
#define HG_SMEM_BYTES (HG_STAGES * 2 * HG_OPB)   // 81920

__global__ __launch_bounds__(128, 1) void gemm_fp16_mma(
    const __half* __restrict__ A, const __half* __restrict__ B,
    float* __restrict__ C, int M, int N, int K)
{
    extern __shared__ uint32_t smw[];
    const int tid  = threadIdx.x;
    const int lane = tid & 31;
    const int wid  = tid >> 5;
    const int bm = blockIdx.y * 128;
    const int bn = blockIdx.x * 128;
    const int NC = K / 32;

    const int wm = (wid & 1) * 64;
    const int wn = (wid >> 1) * 64;
    const int r = lane >> 2;      // 0..7
    const int c = lane & 3;       // 0..3

    const uint32_t smb = sm_u32(smw);

    // ldmatrix per-lane invariants (offsets in halves)
    const int laneRowA = lane & 15;              // row within 16-row A frag
    const int laneKA   = (lane >> 4) * 8;        // k offset (tiles 2,3 -> +8)
    const int laneRowB = (lane & 7) + ((lane >> 4) & 1) * 8;   // row within 16-row B pair
    const int laneKB   = ((lane >> 3) & 1) * 8;  // k offset (tiles 1,3 -> +8)

    // per stage: A 512 chunks(16B) + B 512 chunks; 128 threads x 8
    auto load_chunk = [&](int chunk, int stage) {
        const int k0 = chunk * 32;
        const uint32_t aB = smb + stage * 2 * HG_OPB;
        const uint32_t bB = aB + HG_OPB;
#pragma unroll
        for (int j = 0; j < 8; j++) {
            int idx = tid + j * 128;          // 0..1023
            if (idx < 512) {
                int row = idx >> 2, seg = idx & 3;
                cp16(aB + row * 80 + seg * 16,
                     A + (size_t)(bm + row) * K + k0 + seg * 8);
            } else {
                int t = idx - 512;
                int row = t >> 2, seg = t & 3;
                cp16(bB + row * 80 + seg * 16,
                     B + (size_t)(bn + row) * K + k0 + seg * 8);
            }
        }
    };

    float acc[4][8][4];
#pragma unroll
    for (int i = 0; i < 4; i++)
#pragma unroll
        for (int j = 0; j < 8; j++)
#pragma unroll
            for (int q = 0; q < 4; q++) acc[i][j][q] = 0.f;

#pragma unroll
    for (int s = 0; s < HG_STAGES - 1; s++) {
        load_chunk(s, s);
        asm volatile("cp.async.commit_group;" ::: "memory");
    }

    for (int i = 0; i < NC; i++) {
        asm volatile("cp.async.wait_group %0;" :: "n"(HG_STAGES - 2) : "memory");
        __syncthreads();

        if (i + HG_STAGES - 1 < NC)
            load_chunk(i + HG_STAGES - 1, (i + HG_STAGES - 1) & (HG_STAGES - 1));
        asm volatile("cp.async.commit_group;" ::: "memory");

        const int st = i & (HG_STAGES - 1);
        const uint32_t aBase = smb + st * 2 * HG_OPB;
        const uint32_t bBase = aBase + HG_OPB;

#pragma unroll
        for (int g = 0; g < 2; g++) {          // two k16 groups per BK=32
            const int kh = g * 16;             // half offset within row
            uint32_t af[4][4], bf[8][2];
#pragma unroll
            for (int ii = 0; ii < 4; ii++) {
                const uint32_t addr = aBase +
                    2u * ((wm + ii * 16 + laneRowA) * HG_RSH + kh + laneKA);
                asm volatile(
                    "ldmatrix.sync.aligned.m8n8.x4.shared.b16 {%0,%1,%2,%3}, [%4];"
                    : "=r"(af[ii][0]), "=r"(af[ii][1]),
                      "=r"(af[ii][2]), "=r"(af[ii][3])
                    : "r"(addr));
            }
#pragma unroll
            for (int Jp = 0; Jp < 4; Jp++) {   // pair covers jj = 2Jp, 2Jp+1
                const uint32_t addr = bBase +
                    2u * ((wn + Jp * 16 + laneRowB) * HG_RSH + kh + laneKB);
                asm volatile(
                    "ldmatrix.sync.aligned.m8n8.x4.shared.b16 {%0,%1,%2,%3}, [%4];"
                    : "=r"(bf[2 * Jp][0]), "=r"(bf[2 * Jp][1]),
                      "=r"(bf[2 * Jp + 1][0]), "=r"(bf[2 * Jp + 1][1])
                    : "r"(addr));
            }
#pragma unroll
            for (int ii = 0; ii < 4; ii++)
#pragma unroll
                for (int jj = 0; jj < 8; jj++) {
                    asm volatile(
                        "mma.sync.aligned.m16n8k16.row.col.f32.f16.f16.f32 "
                        "{%0,%1,%2,%3}, {%4,%5,%6,%7}, {%8,%9}, {%0,%1,%2,%3};"
                        : "+f"(acc[ii][jj][0]), "+f"(acc[ii][jj][1]),
                          "+f"(acc[ii][jj][2]), "+f"(acc[ii][jj][3])
                        : "r"(af[ii][0]), "r"(af[ii][1]),
                          "r"(af[ii][2]), "r"(af[ii][3]),
                          "r"(bf[jj][0]), "r"(bf[jj][1]));
                }
        }
        __syncthreads();
    }

    // epilogue: c0:(r,2c) c1:(r,2c+1) c2:(r+8,2c) c3:(r+8,2c+1)
#pragma unroll
    for (int i = 0; i < 4; i++) {
        const int row0 = bm + wm + i * 16 + r;
#pragma unroll
        for (int j = 0; j < 8; j++) {
            const int col = bn + wn + j * 8 + 2 * c;
            *(float2*)&C[(size_t)row0 * N + col] =
                make_float2(acc[i][j][0], acc[i][j][1]);
            *(float2*)&C[(size_t)(row0 + 8) * N + col] =
                make_float2(acc[i][j][2], acc[i][j][3]);
        }
    }
}

// ---------------------------------------------------------------------------
// Depthwise conv(k=4) + SiLU. x half -> xc (fp32, for k3/scan);
// z half -> hAct[:, 512:1024] directly as fp16 (GEMM2 input).
// ---------------------------------------------------------------------------
__global__ __launch_bounds__(256) void conv_silu_kernel(
    const float* __restrict__ xz,
    const float* __restrict__ cxw, const float* __restrict__ cxb,
    const float* __restrict__ czw, const float* __restrict__ czb,
    float* __restrict__ xcout, __half* __restrict__ hact)
{
    int idx = blockIdx.x * 256 + threadIdx.x;
    int c4 = idx & 255;
    int t  = idx >> 8;
    int l  = t & (SEQ - 1);
    int c  = c4 * 4;

    const float* base = xz + (size_t)t * DI + c;
    float4 z4 = make_float4(0.f, 0.f, 0.f, 0.f);
    float4 s0 = (l >= 1)       ? *(const float4*)(base - DI)     : z4;
    float4 s1 =                  *(const float4*)(base);
    float4 s2 = (l + 1 < SEQ)  ? *(const float4*)(base + DI)     : z4;
    float4 s3 = (l + 2 < SEQ)  ? *(const float4*)(base + 2 * DI) : z4;

    float r0[4], r1[4], r2[4], r3[4];
    *(float4*)r0 = s0; *(float4*)r1 = s1; *(float4*)r2 = s2; *(float4*)r3 = s3;

    const bool isx = (c < DH);
    const int  cc  = isx ? c : (c - DH);
    const float* w  = (isx ? cxw : czw) + cc * 4;
    const float* bb = (isx ? cxb : czb) + cc;

    float Wf[16], Bf[4];
    *(float4*)(Wf + 0)  = *(const float4*)(w + 0);
    *(float4*)(Wf + 4)  = *(const float4*)(w + 4);
    *(float4*)(Wf + 8)  = *(const float4*)(w + 8);
    *(float4*)(Wf + 12) = *(const float4*)(w + 12);
    *(float4*)Bf        = *(const float4*)(bb);

    float out[4];
#pragma unroll
    for (int i = 0; i < 4; i++) {
        float v = Bf[i]
                + Wf[i * 4 + 0] * r0[i]
                + Wf[i * 4 + 1] * r1[i]
                + Wf[i * 4 + 2] * r2[i]
                + Wf[i * 4 + 3] * r3[i];
        float sg = __fdividef(1.f, 1.f + __expf(-v));
        out[i] = v * sg;
    }
    if (isx) {
        *(float4*)(xcout + (size_t)t * DH + c) = *(float4*)out;
    } else {
        __half2 h01 = __floats2half2_rn(out[0], out[1]);
        __half2 h23 = __floats2half2_rn(out[2], out[3]);
        __half2* dst = (__half2*)(hact + (size_t)t * DI + c);
        dst[0] = h01;
        dst[1] = h23;
    }
}

// ---------------------------------------------------------------------------
// Fused: x_dbl = xc @ x_proj_w^T (64), LN(64), split Bp/Cp,
//        dt = clip(dt_raw @ dt_proj_w^T,-6,6), delta = softplus(dt+bias)
// ---------------------------------------------------------------------------
__global__ __launch_bounds__(256) void k3_kernel(
    const float* __restrict__ xc,  const float* __restrict__ xpw,
    const float* __restrict__ dtw, const float* __restrict__ dtb,
    const float* __restrict__ lnw, const float* __restrict__ lnb,
    float* __restrict__ delta, float* __restrict__ Bp, float* __restrict__ Cp)
{
    __shared__ float s_xc[16][DH];
    __shared__ float s_db[16][XDB];

    const int tid = threadIdx.x;
    const size_t tok0 = (size_t)blockIdx.x * 16;

    {
        const float4* src = (const float4*)(xc + tok0 * DH);
        float4* dst = (float4*)&s_xc[0][0];
#pragma unroll
        for (int i = 0; i < 8; i++) dst[tid + i * 256] = src[tid + i * 256];
    }
    __syncthreads();

    {
        const int j  = tid & 63;
        const int tg = tid >> 6;
        const float4* wr = (const float4*)(xpw + (size_t)j * DH);
        const float4* x0 = (const float4*)&s_xc[tg * 4 + 0][0];
        const float4* x1 = (const float4*)&s_xc[tg * 4 + 1][0];
        const float4* x2 = (const float4*)&s_xc[tg * 4 + 2][0];
        const float4* x3 = (const float4*)&s_xc[tg * 4 + 3][0];
        float a0 = 0.f, a1 = 0.f, a2 = 0.f, a3 = 0.f;
#pragma unroll 4
        for (int k = 0; k < DH / 4; k++) {
            float4 w4 = wr[k];
            float4 v0 = x0[k], v1 = x1[k], v2 = x2[k], v3 = x3[k];
            a0 += w4.x * v0.x + w4.y * v0.y + w4.z * v0.z + w4.w * v0.w;
            a1 += w4.x * v1.x + w4.y * v1.y + w4.z * v1.z + w4.w * v1.w;
            a2 += w4.x * v2.x + w4.y * v2.y + w4.z * v2.z + w4.w * v2.w;
            a3 += w4.x * v3.x + w4.y * v3.y + w4.z * v3.z + w4.w * v3.w;
        }
        s_db[tg * 4 + 0][j] = a0;
        s_db[tg * 4 + 1][j] = a1;
        s_db[tg * 4 + 2][j] = a2;
        s_db[tg * 4 + 3][j] = a3;
    }
    __syncthreads();

    {
        const int tok = tid >> 4;
        const int q   = tid & 15;
        const int j0  = q * 4;
        float v0 = s_db[tok][j0], v1 = s_db[tok][j0 + 1];
        float v2 = s_db[tok][j0 + 2], v3 = s_db[tok][j0 + 3];
        float s = v0 + v1 + v2 + v3;
        s += __shfl_xor_sync(0xffffffffu, s, 1);
        s += __shfl_xor_sync(0xffffffffu, s, 2);
        s += __shfl_xor_sync(0xffffffffu, s, 4);
        s += __shfl_xor_sync(0xffffffffu, s, 8);
        float mu = s * (1.f / 64.f);
        float d0 = v0 - mu, d1 = v1 - mu, d2 = v2 - mu, d3 = v3 - mu;
        float sq = d0 * d0 + d1 * d1 + d2 * d2 + d3 * d3;
        sq += __shfl_xor_sync(0xffffffffu, sq, 1);
        sq += __shfl_xor_sync(0xffffffffu, sq, 2);
        sq += __shfl_xor_sync(0xffffffffu, sq, 4);
        sq += __shfl_xor_sync(0xffffffffu, sq, 8);
        float rstd = rsqrtf(sq * (1.f / 64.f) + 1e-5f);
        float o[4];
        o[0] = d0 * rstd * lnw[j0]     + lnb[j0];
        o[1] = d1 * rstd * lnw[j0 + 1] + lnb[j0 + 1];
        o[2] = d2 * rstd * lnw[j0 + 2] + lnb[j0 + 2];
        o[3] = d3 * rstd * lnw[j0 + 3] + lnb[j0 + 3];
        s_db[tok][j0] = o[0]; s_db[tok][j0 + 1] = o[1];
        s_db[tok][j0 + 2] = o[2]; s_db[tok][j0 + 3] = o[3];
        if (q >= 8) {
            size_t tk = tok0 + tok;
            int base = j0 - DTR;
#pragma unroll
            for (int i = 0; i < 4; i++) {
                int jj = base + i;
                if (jj < NST) Bp[tk * NST + jj]         = o[i];
                else          Cp[tk * NST + (jj - NST)] = o[i];
            }
        }
    }
    __syncthreads();

    {
#pragma unroll
        for (int half = 0; half < 2; half++) {
            const int dch = tid + half * 256;
            const float4* wr = (const float4*)(dtw + (size_t)dch * DTR);
            float4 w4[8];
#pragma unroll
            for (int i = 0; i < 8; i++) w4[i] = wr[i];
            const float bias = dtb[dch];
#pragma unroll
            for (int tok = 0; tok < 16; tok++) {
                const float4* xr = (const float4*)&s_db[tok][0];
                float acc = 0.f;
#pragma unroll
                for (int i = 0; i < 8; i++) {
                    float4 x4 = xr[i];
                    acc += w4[i].x * x4.x + w4[i].y * x4.y
                         + w4[i].z * x4.z + w4[i].w * x4.w;
                }
                float v = fminf(fmaxf(acc, -6.f), 6.f) + bias;
                float sp = fmaxf(v, 0.f) + log1pf(__expf(-fabsf(v)));
                delta[(tok0 + tok) * (size_t)DH + dch] = sp;
            }
        }
    }
}

// ---------------------------------------------------------------------------
// Selective scan -> writes y directly as fp16 into hAct[:, :512].
// Channel (b,d) = 16 lanes (one per state), 2 channels/warp.
// ---------------------------------------------------------------------------
__global__ __launch_bounds__(256) void scan_kernel(
    const float* __restrict__ delta, const float* __restrict__ xc,
    const float* __restrict__ Bp,    const float* __restrict__ Cp,
    const float* __restrict__ A_log, const float* __restrict__ D_param,
    __half* __restrict__ hact)
{
    const int tid = threadIdx.x;
    const int ch  = blockIdx.x * 16 + (tid >> 4);
    const int n   = tid & 15;
    const int b   = ch >> 9;
    const int d   = ch & 511;

    const float a  = -__expf(A_log[d * NST + n]);
    const float Dd = D_param[d];

    const float* dl = delta + ((size_t)b * SEQ) * DH + d;
    const float* ul = xc    + ((size_t)b * SEQ) * DH + d;
    const float* Bl = Bp    + ((size_t)b * SEQ) * NST + n;
    const float* Cl = Cp    + ((size_t)b * SEQ) * NST + n;
    __half*      yl = hact  + ((size_t)b * SEQ) * DI + d;

    float h = 0.f;
    float dv[2][4], uv[2][4], bv[2][4], cv[2][4];

#pragma unroll
    for (int i = 0; i < 4; i++) {
        dv[0][i] = dl[i * DH];  uv[0][i] = ul[i * DH];
        bv[0][i] = Bl[i * NST]; cv[0][i] = Cl[i * NST];
    }

    for (int l0 = 0; l0 < SEQ; l0 += 4) {
        const int cur = (l0 >> 2) & 1;
        const int nxt = cur ^ 1;
        if (l0 + 4 < SEQ) {
            const float* dn = dl + 4 * DH;
            const float* un = ul + 4 * DH;
            const float* bn = Bl + 4 * NST;
            const float* cn = Cl + 4 * NST;
#pragma unroll
            for (int i = 0; i < 4; i++) {
                dv[nxt][i] = dn[i * DH];  uv[nxt][i] = un[i * DH];
                bv[nxt][i] = bn[i * NST]; cv[nxt][i] = cn[i * NST];
            }
        }
#pragma unroll
        for (int i = 0; i < 4; i++) {
            float dvi = dv[cur][i];
            float da  = __expf(dvi * a);
            h = fmaf(da, h, dvi * uv[cur][i] * bv[cur][i]);
            float p = h * cv[cur][i];
            p += __shfl_xor_sync(0xffffffffu, p, 8);
            p += __shfl_xor_sync(0xffffffffu, p, 4);
            p += __shfl_xor_sync(0xffffffffu, p, 2);
            p += __shfl_xor_sync(0xffffffffu, p, 1);
            if (n == 0) yl[i * DI] = __float2half(fmaf(Dd, uv[cur][i], p));
        }
        dl += 4 * DH; ul += 4 * DH; Bl += 4 * NST; Cl += 4 * NST; yl += 4 * DI;
    }
}

// ---------------------------------------------------------------------------
extern "C" void kernel_launch(void* const* d_in, const int* in_sizes, int n_in,
                              void* d_out, int out_size)
{
    const float* hs   = (const float*)d_in[0];
    const float* ipw  = (const float*)d_in[1];
    const float* xpw  = (const float*)d_in[2];
    const float* dtw  = (const float*)d_in[3];
    const float* dtb  = (const float*)d_in[4];
    const float* alog = (const float*)d_in[5];
    const float* Dp   = (const float*)d_in[6];
    const float* cxw  = (const float*)d_in[7];
    const float* cxb  = (const float*)d_in[8];
    const float* czw  = (const float*)d_in[9];
    const float* czb  = (const float*)d_in[10];
    const float* lnw  = (const float*)d_in[11];
    const float* lnb  = (const float*)d_in[12];
    const float* opw  = (const float*)d_in[13];

    float* pool = nullptr;
    cudaGetSymbolAddress((void**)&pool, g_pool);
    float* xz    = pool + OFF_XZ;
    float* xc    = pool + OFF_XC;
    float* delta = pool + OFF_DELTA;
    float* Bpp   = pool + OFF_BP;
    float* Cpp   = pool + OFF_CP;
    __half* hAct = (__half*)(pool + OFF_HACT);   // dedicated fp16 buffers
    __half* hW   = (__half*)(pool + OFF_HW);

    cudaFuncSetAttribute(gemm_fp16_mma,
                         cudaFuncAttributeMaxDynamicSharedMemorySize,
                         HG_SMEM_BYTES);

    // 1) halve GEMM1 inputs (hAct free until conv; re-laid per-token later)
    to_half_kernel<<<(BL * DM / 4 + 255) / 256, 256>>>(hs, hAct, BL * DM / 4);
    to_half_kernel<<<(DI * DM / 4 + 255) / 256, 256>>>(ipw, hW, DI * DM / 4);
    // 2) xz = hs @ ipw^T   [16384,1024]
    gemm_fp16_mma<<<dim3(DI / 128, BL / 128), 128, HG_SMEM_BYTES>>>(
        hAct, hW, xz, BL, DI, DM);
    // 3) depthwise conv + silu (x -> xc fp32; zc -> hAct[:,512:] fp16)
    conv_silu_kernel<<<BL, 256>>>(xz, cxw, cxb, czw, czb, xc, hAct);
    // 4) x_proj + LN + dt_proj + softplus
    k3_kernel<<<BL / 16, 256>>>(xc, xpw, dtw, dtb, lnw, lnb, delta, Bpp, Cpp);
    // 5) selective scan -> hAct[:, :512] fp16 (includes +xc*D)
    scan_kernel<<<128, 256>>>(delta, xc, Bpp, Cpp, alog, Dp, hAct);
    // 6) halve GEMM2 weights
    to_half_kernel<<<(DM * DI / 4 + 255) / 256, 256>>>(opw, hW, DM * DI / 4);
    // 7) out = [y|zc] @ opw^T  [16384,512]
    gemm_fp16_mma<<<dim3(DM / 128, BL / 128), 128, HG_SMEM_BYTES>>>(
        hAct, hW, (float*)d_out, BL, DM, DI);
}